// round 12
// baseline (speedup 1.0000x reference)
#include <cuda_runtime.h>
#include <cstdint>

// Focal CTC loss — single-warp-per-direction, linear domain, per-lane exponents.
// grid = 2B = 128 one-warp CTAs. dir = bid&1, b = bid>>1.
// Lane holds pairs j = 4*lane .. 4*lane+3 (states 2j, 2j+1) as linear fp32
// relative to per-lane exponent eAcc (value = lin * 2^eAcc). Renorm every 2
// steps. Cross-lane exchange: raw (lin, eAcc) via shfl + exact 2^d rescale,
// with adoption (virgin lane) and rebase (incoming dominates) reconciliation.
// Emissions: per-lane __ldcg, PF=8 register prefetch, ex2'd one step early;
// the linear pV values ARE exp(lp[t,ch_j]) -> focal-weight sums fall out free.
// fwd covers rows [0,Tm], bwd rows [Tm+1,len-1]; second finisher per sample
// combines ll = LSE_s(alpha_Tm + beta_Tm) and focal weights; final scalar
// factorizes: mean(outer(w,loss)) = mean(loss)*mean(w).

#define CFIX  256
#define PF    8
#define NEG2  (-1e30f)
#define LOG2E 1.4426950408889634f
#define LN2   0.6931471805599453f

__device__ float    g_mid[64][2][128][2];
__device__ float    g_tps[64][2][128];
__device__ unsigned g_done[64];
__device__ float    g_loss[64];
__device__ float    g_wsum[64];
__device__ unsigned g_ctr = 0;

__device__ __forceinline__ float ex2f(float x){ float y; asm("ex2.approx.ftz.f32 %0,%1;":"=f"(y):"f"(x)); return y; }
__device__ __forceinline__ float lg2f(float x){ float y; asm("lg2.approx.ftz.f32 %0,%1;":"=f"(y):"f"(x)); return y; }

__device__ __forceinline__ void finalize(float* out, int B, int L)
{
    __threadfence();
    unsigned v = atomicAdd(&g_ctr, 1u);
    if (v == (unsigned)(B - 1)) {
        g_ctr = 0;
        __threadfence();
        float ls = 0.0f, ws = 0.0f;
        for (int i = 0; i < B; i++) {
            ls += __ldcg(&g_loss[i]);
            ws += __ldcg(&g_wsum[i]);
        }
        out[0] = (ls / (float)B) * (ws / ((float)B * (float)L));
    }
}

__global__ __launch_bounds__(32, 1)
void focal_ctc_kernel(const float* __restrict__ lp,      // (T,B,C)
                      const int*   __restrict__ targets, // (B*L)
                      const int*   __restrict__ in_len,  // (B)
                      const int*   __restrict__ tg_len,  // (B)
                      float*       __restrict__ out,
                      int T, int B, int L)
{
    const int lane = threadIdx.x;
    const int bid  = blockIdx.x;
    const int dir  = bid & 1, b = bid >> 1;
    const int len  = in_len[b], tl = tg_len[b];
    const int bL   = b * L;
    const int Tm   = len >> 1;
    const int nB   = len - 1 - Tm;
    const size_t tstr = (size_t)B * CFIX;
    const float* base = lp + (size_t)b * CFIX;

    const int j0 = 4 * lane;
    int   ch0, ch1, ch2, ch3;
    float mV0, mV1, mV2, mV3;
    float alf0, alf1, alf2, alf3;     // fwd: skip into v_j from v_{j-1}
    float alN0, alN1, alN2, alN3;     // bwd: skip from v_j to v_{j+1}
    {
        int jp;
        jp = j0;     ch0 = (jp < L) ? targets[bL + jp] : 0; mV0 = (jp < L) ? 1.f : 0.f;
        alf0 = (jp >= 1 && jp < L && targets[bL + jp] != targets[bL + jp - 1]) ? 1.f : 0.f;
        alN0 = (jp + 1 < L && targets[bL + jp + 1] != targets[bL + jp]) ? 1.f : 0.f;
        jp = j0 + 1; ch1 = (jp < L) ? targets[bL + jp] : 0; mV1 = (jp < L) ? 1.f : 0.f;
        alf1 = (jp >= 1 && jp < L && targets[bL + jp] != targets[bL + jp - 1]) ? 1.f : 0.f;
        alN1 = (jp + 1 < L && targets[bL + jp + 1] != targets[bL + jp]) ? 1.f : 0.f;
        jp = j0 + 2; ch2 = (jp < L) ? targets[bL + jp] : 0; mV2 = (jp < L) ? 1.f : 0.f;
        alf2 = (jp >= 1 && jp < L && targets[bL + jp] != targets[bL + jp - 1]) ? 1.f : 0.f;
        alN2 = (jp + 1 < L && targets[bL + jp + 1] != targets[bL + jp]) ? 1.f : 0.f;
        jp = j0 + 3; ch3 = (jp < L) ? targets[bL + jp] : 0; mV3 = (jp < L) ? 1.f : 0.f;
        alf3 = (jp >= 1 && jp < L && targets[bL + jp] != targets[bL + jp - 1]) ? 1.f : 0.f;
        alN3 = (jp + 1 < L && targets[bL + jp + 1] != targets[bL + jp]) ? 1.f : 0.f;
    }

    float rB[PF], rA0[PF], rA1[PF], rA2[PF], rA3[PF];   // raw log_probs prefetch
    float pB, pA0, pA1, pA2, pA3;                       // current linear emissions
    float u0, u1, u2, u3, v0, v1, v2, v3;               // alpha/beta (linear)
    float acc0 = 0.f, acc1 = 0.f, acc2 = 0.f, acc3 = 0.f;
    int   eAcc = 0;
    bool  zf;

#define LOADF(SL, ROW) { const float* s_ = base + (size_t)(ROW) * tstr; \
    rB[SL]=__ldcg(s_); rA0[SL]=__ldcg(s_+ch0); rA1[SL]=__ldcg(s_+ch1); \
    rA2[SL]=__ldcg(s_+ch2); rA3[SL]=__ldcg(s_+ch3); }
#define CONVS(SL) { pB = ex2f(rB[SL]*LOG2E); \
    pA0 = mV0*ex2f(rA0[SL]*LOG2E); pA1 = mV1*ex2f(rA1[SL]*LOG2E); \
    pA2 = mV2*ex2f(rA2[SL]*LOG2E); pA3 = mV3*ex2f(rA3[SL]*LOG2E); }
#define RENORM() { \
    float m_ = fmaxf(fmaxf(fmaxf(u0,u1),fmaxf(u2,u3)), fmaxf(fmaxf(v0,v1),fmaxf(v2,v3))); \
    if (m_ > 0.f) { zf = false; \
        int e_ = (int)(__float_as_uint(m_) >> 23) - 127; \
        float s_ = __uint_as_float((unsigned)(127 - e_) << 23); \
        eAcc += e_; u0*=s_;u1*=s_;u2*=s_;u3*=s_; v0*=s_;v1*=s_;v2*=s_;v3*=s_; } }
#define SCALE8(S) { u0*=(S);u1*=(S);u2*=(S);u3*=(S);v0*=(S);v1*=(S);v2*=(S);v3*=(S); }

    if (dir == 0) {
        // ======================= FORWARD =======================
        #pragma unroll
        for (int i = 0; i < PF; i++) { int r = i > Tm ? Tm : i; LOADF(i, r) }
        CONVS(0)
        u0=u1=u2=u3=0.f; v0=v1=v2=v3=0.f;
        if (lane == 0) { u0 = pB; v0 = pA0; }
        acc0 = pA0; acc1 = pA1; acc2 = pA2; acc3 = pA3;
        zf = (lane != 0);
        CONVS(1)

#define FSTEP(SL, SLN, TCUR, DOREN) { \
    float vnb = __shfl_up_sync(0xFFFFFFFFu, v3, 1); \
    int   enb = __shfl_up_sync(0xFFFFFFFFu, eAcc, 1); \
    float avm = 0.f; \
    if (lane != 0 && vnb != 0.f) { \
        if (zf) { eAcc = enb; zf = false; avm = vnb; } \
        else { int d_ = enb - eAcc; \
            if (d_ > 60) { float s2_ = (d_ > 126) ? 0.f : __uint_as_float((unsigned)(127 - d_) << 23); \
                SCALE8(s2_); eAcc = enb; avm = vnb; } \
            else { float sc_ = (d_ < -126) ? 0.f : __uint_as_float((unsigned)(127 + d_) << 23); \
                avm = vnb * sc_; } } } \
    float nu0 = (u0 + avm) * pB; \
    float nv0 = fmaf(alf0, avm, v0 + u0) * pA0; \
    float nu1 = (u1 + v0) * pB; \
    float nv1 = fmaf(alf1, v0, v1 + u1) * pA1; \
    float nu2 = (u2 + v1) * pB; \
    float nv2 = fmaf(alf2, v1, v2 + u2) * pA2; \
    float nu3 = (u3 + v2) * pB; \
    float nv3 = fmaf(alf3, v2, v3 + u3) * pA3; \
    acc0 += pA0; acc1 += pA1; acc2 += pA2; acc3 += pA3; \
    u0=nu0;u1=nu1;u2=nu2;u3=nu3; v0=nv0;v1=nv1;v2=nv2;v3=nv3; \
    { int rl_ = (TCUR) + PF; if (rl_ > Tm) rl_ = Tm; LOADF(SL, rl_) } \
    CONVS(SLN) \
    if (DOREN) RENORM() }

        int t = 1;
        for (; t + 7 <= Tm; t += 8) {
            FSTEP(1,2,t  ,1) FSTEP(2,3,t+1,0) FSTEP(3,4,t+2,1) FSTEP(4,5,t+3,0)
            FSTEP(5,6,t+4,1) FSTEP(6,7,t+5,0) FSTEP(7,0,t+6,1) FSTEP(0,1,t+7,0)
        }
        if (t     <= Tm) FSTEP(1,2,t  ,1)
        if (t + 1 <= Tm) FSTEP(2,3,t+1,0)
        if (t + 2 <= Tm) FSTEP(3,4,t+2,1)
        if (t + 3 <= Tm) FSTEP(4,5,t+3,0)
        if (t + 4 <= Tm) FSTEP(5,6,t+4,1)
        if (t + 5 <= Tm) FSTEP(6,7,t+5,0)
        if (t + 6 <= Tm) FSTEP(7,0,t+6,1)
#undef FSTEP
    } else {
        // ======================= BACKWARD =======================
        #pragma unroll
        for (int i = 0; i < PF; i++) {
            int kk = i > nB - 1 ? nB - 1 : i;
            LOADF(i, len - 1 - kk)
        }
        CONVS(0)
        u0 = (j0     == tl) ? 1.f : 0.f;  v0 = (j0     == tl - 1) ? 1.f : 0.f;
        u1 = (j0 + 1 == tl) ? 1.f : 0.f;  v1 = (j0 + 1 == tl - 1) ? 1.f : 0.f;
        u2 = (j0 + 2 == tl) ? 1.f : 0.f;  v2 = (j0 + 2 == tl - 1) ? 1.f : 0.f;
        u3 = (j0 + 3 == tl) ? 1.f : 0.f;  v3 = (j0 + 3 == tl - 1) ? 1.f : 0.f;
        zf = !(u0 != 0.f || u1 != 0.f || u2 != 0.f || u3 != 0.f ||
               v0 != 0.f || v1 != 0.f || v2 != 0.f || v3 != 0.f);

#define BSTEP(SL, SLN, KCUR, DOREN) { \
    float unb = __shfl_down_sync(0xFFFFFFFFu, u0, 1); \
    float vnb = __shfl_down_sync(0xFFFFFFFFu, v0, 1); \
    float pnb = __shfl_down_sync(0xFFFFFFFFu, pA0, 1); \
    int   enb = __shfl_down_sync(0xFFFFFFFFu, eAcc, 1); \
    if (lane == 31) { unb = 0.f; vnb = 0.f; } \
    if (unb != 0.f || vnb != 0.f) { \
        if (zf) { eAcc = enb; zf = false; } \
        else { int d_ = enb - eAcc; \
            if (d_ > 60) { float s2_ = (d_ > 126) ? 0.f : __uint_as_float((unsigned)(127 - d_) << 23); \
                SCALE8(s2_); eAcc = enb; } \
            else { float sc_ = (d_ < -126) ? 0.f : __uint_as_float((unsigned)(127 + d_) << 23); \
                unb *= sc_; vnb *= sc_; } } } \
    float w0 = v0 * pA0, w1 = v1 * pA1, w2 = v2 * pA2, w3 = v3 * pA3; \
    float wn = vnb * pnb; \
    float nu0 = fmaf(u0, pB, w0), nu1 = fmaf(u1, pB, w1); \
    float nu2 = fmaf(u2, pB, w2), nu3 = fmaf(u3, pB, w3); \
    float nv0 = fmaf(alN0, w1, fmaf(u1, pB, w0)); \
    float nv1 = fmaf(alN1, w2, fmaf(u2, pB, w1)); \
    float nv2 = fmaf(alN2, w3, fmaf(u3, pB, w2)); \
    float nv3 = fmaf(alN3, wn, fmaf(unb, pB, w3)); \
    acc0 += pA0; acc1 += pA1; acc2 += pA2; acc3 += pA3; \
    u0=nu0;u1=nu1;u2=nu2;u3=nu3; v0=nv0;v1=nv1;v2=nv2;v3=nv3; \
    { int kl_ = (KCUR) + PF; if (kl_ > nB - 1) kl_ = nB - 1; LOADF(SL, len - 1 - kl_) } \
    CONVS(SLN) \
    if (DOREN) RENORM() }

        int k = 0;
        for (; k + 7 <= nB - 1; k += 8) {
            BSTEP(0,1,k  ,0) BSTEP(1,2,k+1,1) BSTEP(2,3,k+2,0) BSTEP(3,4,k+3,1)
            BSTEP(4,5,k+4,0) BSTEP(5,6,k+5,1) BSTEP(6,7,k+6,0) BSTEP(7,0,k+7,1)
        }
        if (k     <= nB - 1) BSTEP(0,1,k  ,0)
        if (k + 1 <= nB - 1) BSTEP(1,2,k+1,1)
        if (k + 2 <= nB - 1) BSTEP(2,3,k+2,0)
        if (k + 3 <= nB - 1) BSTEP(3,4,k+3,1)
        if (k + 4 <= nB - 1) BSTEP(4,5,k+4,0)
        if (k + 5 <= nB - 1) BSTEP(5,6,k+5,1)
        if (k + 6 <= nB - 1) BSTEP(6,7,k+6,0)
#undef BSTEP
    }

    // ---- publish mid-state (log2) + tps partials ----
    {
        float ea = (float)eAcc;
        float gu, gv;
        gu = (u0 > 0.f) ? ea + lg2f(u0) : NEG2;  gv = (v0 > 0.f) ? ea + lg2f(v0) : NEG2;
        g_mid[b][dir][j0    ][0] = gu; g_mid[b][dir][j0    ][1] = gv; g_tps[b][dir][j0    ] = acc0;
        gu = (u1 > 0.f) ? ea + lg2f(u1) : NEG2;  gv = (v1 > 0.f) ? ea + lg2f(v1) : NEG2;
        g_mid[b][dir][j0 + 1][0] = gu; g_mid[b][dir][j0 + 1][1] = gv; g_tps[b][dir][j0 + 1] = acc1;
        gu = (u2 > 0.f) ? ea + lg2f(u2) : NEG2;  gv = (v2 > 0.f) ? ea + lg2f(v2) : NEG2;
        g_mid[b][dir][j0 + 2][0] = gu; g_mid[b][dir][j0 + 2][1] = gv; g_tps[b][dir][j0 + 2] = acc2;
        gu = (u3 > 0.f) ? ea + lg2f(u3) : NEG2;  gv = (v3 > 0.f) ? ea + lg2f(v3) : NEG2;
        g_mid[b][dir][j0 + 3][0] = gu; g_mid[b][dir][j0 + 3][1] = gv; g_tps[b][dir][j0 + 3] = acc3;
    }
    __threadfence();
    unsigned sflag = 0;
    if (lane == 0) sflag = atomicAdd(&g_done[b], 1u);
    sflag = __shfl_sync(0xFFFFFFFFu, sflag, 0);

    if (sflag == 1) {                    // second finisher: combine this sample
        float cu[4], cv[4];
        float M = NEG2;
        #pragma unroll
        for (int p = 0; p < 4; p++) {
            int jp = j0 + p;
            float a0 = __ldcg(&g_mid[b][0][jp][0]), a1 = __ldcg(&g_mid[b][0][jp][1]);
            float b0 = __ldcg(&g_mid[b][1][jp][0]), b1 = __ldcg(&g_mid[b][1][jp][1]);
            cu[p] = a0 + b0;  cv[p] = a1 + b1;
            M = fmaxf(M, fmaxf(cu[p], cv[p]));
        }
        #pragma unroll
        for (int o = 16; o; o >>= 1) M = fmaxf(M, __shfl_xor_sync(0xFFFFFFFFu, M, o));
        float s = 0.f, wgt = 0.f;
        #pragma unroll
        for (int p = 0; p < 4; p++) {
            s += ex2f(cu[p] - M) + ex2f(cv[p] - M);
            int jp = j0 + p;
            if (jp < L) {
                float tps = __ldcg(&g_tps[b][0][jp]) + __ldcg(&g_tps[b][1][jp]);
                float om  = 1.0f - tps * (1.0f / (float)T);
                wgt += om * om;                  // GAMMA = 2
            }
        }
        #pragma unroll
        for (int o = 16; o; o >>= 1) {
            s   += __shfl_xor_sync(0xFFFFFFFFu, s, o);
            wgt += __shfl_xor_sync(0xFFFFFFFFu, wgt, o);
        }
        if (lane == 0) {
            float ll = (M + lg2f(s)) * LN2;
            g_loss[b] = (ll > -5e29f) ? -ll : 0.0f;   // zero_infinity
            g_wsum[b] = wgt;
            g_done[b] = 0;                            // reset for graph replay
            finalize(out, B, L);
        }
    }
#undef LOADF
#undef CONVS
#undef RENORM
#undef SCALE8
}

extern "C" void kernel_launch(void* const* d_in, const int* in_sizes, int n_in,
                              void* d_out, int out_size)
{
    const float* lp      = (const float*)d_in[0];
    const int*   targets = (const int*)d_in[1];
    const int*   in_len  = (const int*)d_in[2];
    const int*   tg_len  = (const int*)d_in[3];

    int B = in_sizes[2];                 // 64
    int L = in_sizes[1] / B;             // 100
    int T = in_sizes[0] / (B * CFIX);    // 1000

    focal_ctc_kernel<<<2 * B, 32>>>(lp, targets, in_len, tg_len, (float*)d_out, T, B, L);
}

// round 13
// speedup vs baseline: 2.1367x; 2.1367x over previous
#include <cuda_runtime.h>
#include <cstdint>

// Focal CTC loss — bidirectional split scan, 4 timesteps per barrier using
// interval-local LINEAR-domain pyramid (pure FMA on the chain).
// grid = 2B (dir = bid&1, b = bid>>1), block = 160.
//   Warps 0-3: thread j = pair j (states 2j, 2j+1). Per interval: read 4
//   neighbor pairs (log2) from smem, convert all inputs to linear relative to
//   the local max m (ex2), run a 4-step redundant pyramid in pure FMA
//   (zero-preserving; emissions <= 1 so bounded), convert own pair back with
//   lg2, store. Emissions come from a 16-deep cp.async full-row ring (warp 4).
//   Own-channel linear emissions double as the focal-weight sum (free).
// fwd covers rows [0,Tm], bwd rows [Tm+1,len-1]; second finisher per sample
// combines ll = LSE_s(alpha_Tm + beta_Tm) + focal weights. Final scalar
// factorizes: mean(outer(w,loss)) = mean(loss)*mean(w).

#define CFIX  256
#define DEPTH 16
#define NEG2  (-1e30f)
#define LOG2E 1.4426950408889634f
#define LN2   0.6931471805599453f

__device__ float    g_mid[64][2][128][2];
__device__ float    g_tps[64][2][128];
__device__ unsigned g_done[64];
__device__ float    g_loss[64];
__device__ float    g_wsum[64];
__device__ unsigned g_ctr = 0;

__device__ __forceinline__ float ex2f(float x){ float y; asm("ex2.approx.ftz.f32 %0,%1;":"=f"(y):"f"(x)); return y; }
__device__ __forceinline__ float lg2f(float x){ float y; asm("lg2.approx.ftz.f32 %0,%1;":"=f"(y):"f"(x)); return y; }

// single-step log-domain forms (tail steps only)
__device__ __forceinline__ float lse2p(float a, float b, float e) {
    float hi = fmaxf(a, b), lo = fminf(a, b);
    return fmaf(e, LOG2E, hi + lg2f(1.0f + ex2f(lo - hi)));
}
__device__ __forceinline__ float lse3p(float a, float b, float c, float e) {
    float hi = fmaxf(a, b), lo = fminf(a, b);
    float m  = fmaxf(hi, c), o1 = fminf(hi, c);
    return fmaf(e, LOG2E, m + lg2f(1.0f + ex2f(o1 - m) + ex2f(lo - m)));
}
__device__ __forceinline__ float lse2(float a, float b) {
    float hi = fmaxf(a, b), lo = fminf(a, b);
    return hi + lg2f(1.0f + ex2f(lo - hi));
}
__device__ __forceinline__ float lse3(float a, float b, float c) {
    float hi = fmaxf(a, b), lo = fminf(a, b);
    float m  = fmaxf(hi, c), o1 = fminf(hi, c);
    return m + lg2f(1.0f + ex2f(o1 - m) + ex2f(lo - m));
}

__device__ __forceinline__ void finalize(float* out, int B, int L)
{
    __threadfence();
    unsigned v = atomicAdd(&g_ctr, 1u);
    if (v == (unsigned)(B - 1)) {
        g_ctr = 0;
        __threadfence();
        float ls = 0.0f, ws = 0.0f;
        for (int i = 0; i < B; i++) {
            ls += __ldcg(&g_loss[i]);
            ws += __ldcg(&g_wsum[i]);
        }
        out[0] = (ls / (float)B) * (ws / ((float)B * (float)L));
    }
}

__global__ __launch_bounds__(160, 1)
void focal_ctc_kernel(const float* __restrict__ lp,      // (T,B,C)
                      const int*   __restrict__ targets, // (B*L)
                      const int*   __restrict__ in_len,  // (B)
                      const int*   __restrict__ tg_len,  // (B)
                      float*       __restrict__ out,
                      int T, int B, int L)
{
    __shared__ __align__(16) float ring[DEPTH][CFIX];  // 16 KB row ring
    __shared__ float2 ab[2][132];   // fwd: pair p at [4+p] (front pads 0-3); bwd: pair p at [p] (end pads 128-131)
    __shared__ float  redm[4], reds[4], redww[4];
    __shared__ unsigned sflag;

    const int tid = threadIdx.x, w = tid >> 5, lane = tid & 31;
    const int bid = blockIdx.x;
    const int dir = bid & 1, b = bid >> 1;
    const int len = in_len[b], tl = tg_len[b];
    const int bL  = b * L;
    const int Tm  = len >> 1;
    const int nB  = len - 1 - Tm;
    const size_t tstr = (size_t)B * CFIX;
    const float* rowb = lp + (size_t)b * CFIX;

    uint32_t ringA = (uint32_t)__cvta_generic_to_shared(&ring[0][0]);
    #define ISSUE(SLOT, ROW)                                                        \
    {                                                                               \
        const float* s0_ = rowb + (size_t)(ROW) * tstr + lane * 4;                  \
        uint32_t d0_ = ringA + (uint32_t)(SLOT) * (CFIX * 4) + lane * 16;           \
        asm volatile("cp.async.ca.shared.global [%0], [%1], 16;" :: "r"(d0_),       "l"(s0_) : "memory"); \
        asm volatile("cp.async.ca.shared.global [%0], [%1], 16;" :: "r"(d0_ + 512), "l"(s0_ + 128) : "memory"); \
    }

    // pads (both layouts)
    if (tid < 4) { ab[0][tid] = make_float2(NEG2, NEG2); ab[1][tid] = make_float2(NEG2, NEG2); }
    if (tid >= 128 && tid < 132) { ab[0][tid] = make_float2(NEG2, NEG2); ab[1][tid] = make_float2(NEG2, NEG2); }

    const int j = tid;                       // pair index (compute warps)
    const bool cw = (w < 4);
    const bool hasU = cw && (j <= L);
    const bool hasV = cw && (j <= L - 1);

    float aU = NEG2, aV = NEG2, acc = 0.0f;

    if (dir == 0) {
        // ======================= FORWARD =======================
        int c0 = 0, c1 = 0, c2 = 0, c3 = 0, c4f = 0;
        float af0 = 0.f, af1 = 0.f, af2 = 0.f, af3 = 0.f;
        if (cw) {
            if (j     < L)            c0  = targets[bL + j];
            if (j - 1 >= 0 && j - 1 < L) c1 = targets[bL + j - 1];
            if (j - 2 >= 0 && j - 2 < L) c2 = targets[bL + j - 2];
            if (j - 3 >= 0 && j - 3 < L) c3 = targets[bL + j - 3];
            if (j - 4 >= 0 && j - 4 < L) c4f = targets[bL + j - 4];
            af0 = (j >= 1 && j     < L     && c0 != c1)  ? 1.f : 0.f;
            af1 = (j >= 2 && j - 1 < L     && c1 != c2)  ? 1.f : 0.f;
            af2 = (j >= 3 && j - 2 < L     && c2 != c3)  ? 1.f : 0.f;
            af3 = (j >= 4 && j - 3 < L     && c3 != c4f) ? 1.f : 0.f;
        }
        if (w == 4) {
            #pragma unroll
            for (int i = 0; i < 13; i++) {
                if (i <= Tm) ISSUE(i & 15, i)
                asm volatile("cp.async.commit_group;" ::: "memory");
            }
            asm volatile("cp.async.wait_group 8;" ::: "memory");   // rows 0..4 done
        }
        __syncthreads();
        // t = 0
        if (cw) {
            if (j == 0) { aU = ring[0][0] * LOG2E; aV = ring[0][c0] * LOG2E; }
            acc = ex2f(ring[0][c0] * LOG2E);
            ab[0][4 + j] = make_float2(aU, aV);
        }
        int rb = 0, t = 1;
        for (; t + 3 <= Tm; t += 4) {
            __syncthreads();
            if (w == 4) {
                #pragma unroll
                for (int q = 0; q < 4; q++) {
                    int r = t + 12 + q;
                    if (r <= Tm) ISSUE(r & 15, r)
                    asm volatile("cp.async.commit_group;" ::: "memory");
                }
                asm volatile("cp.async.wait_group 8;" ::: "memory");
            } else if (cw) {
                float2 n1 = ab[rb][3 + j], n2 = ab[rb][2 + j];
                float2 n3 = ab[rb][1 + j], n4 = ab[rb][j];
                float m = fmaxf(fmaxf(fmaxf(aU, aV), fmaxf(n1.x, n1.y)),
                                fmaxf(fmaxf(n2.x, n2.y),
                                      fmaxf(fmaxf(n3.x, n3.y), n4.y)));
                float U0 = ex2f(aU - m),   V0 = ex2f(aV - m);
                float U1 = ex2f(n1.x - m), V1 = ex2f(n1.y - m);
                float U2 = ex2f(n2.x - m), V2 = ex2f(n2.y - m);
                float U3 = ex2f(n3.x - m), V3 = ex2f(n3.y - m);
                float V4 = ex2f(n4.y - m);
                const float* R0 = &ring[(t    ) & 15][0];
                const float* R1 = &ring[(t + 1) & 15][0];
                const float* R2 = &ring[(t + 2) & 15][0];
                const float* R3 = &ring[(t + 3) & 15][0];
                float pB0 = ex2f(R0[0] * LOG2E), pB1 = ex2f(R1[0] * LOG2E);
                float pB2 = ex2f(R2[0] * LOG2E), pB3 = ex2f(R3[0] * LOG2E);
                float pA00 = ex2f(R0[c0] * LOG2E), pA01 = ex2f(R0[c1] * LOG2E);
                float pA02 = ex2f(R0[c2] * LOG2E), pA03 = ex2f(R0[c3] * LOG2E);
                float pA10 = ex2f(R1[c0] * LOG2E), pA11 = ex2f(R1[c1] * LOG2E);
                float pA12 = ex2f(R1[c2] * LOG2E);
                float pA20 = ex2f(R2[c0] * LOG2E), pA21 = ex2f(R2[c1] * LOG2E);
                float pA30 = ex2f(R3[c0] * LOG2E);
                acc += pA00 + pA10 + pA20 + pA30;
                // step 1 (row t): pairs j, j-1, j-2, j-3
                float tU0 = (U0 + V1) * pB0, tV0 = fmaf(af0, V1, V0 + U0) * pA00;
                float tU1 = (U1 + V2) * pB0, tV1 = fmaf(af1, V2, V1 + U1) * pA01;
                float tU2 = (U2 + V3) * pB0, tV2 = fmaf(af2, V3, V2 + U2) * pA02;
                float tU3 = (U3 + V4) * pB0, tV3 = fmaf(af3, V4, V3 + U3) * pA03;
                // step 2 (row t+1): pairs j, j-1, j-2
                float sU0 = (tU0 + tV1) * pB1, sV0 = fmaf(af0, tV1, tV0 + tU0) * pA10;
                float sU1 = (tU1 + tV2) * pB1, sV1 = fmaf(af1, tV2, tV1 + tU1) * pA11;
                float sU2 = (tU2 + tV3) * pB1, sV2 = fmaf(af2, tV3, tV2 + tU2) * pA12;
                // step 3 (row t+2): pairs j, j-1
                float rU0 = (sU0 + sV1) * pB2, rV0 = fmaf(af0, sV1, sV0 + sU0) * pA20;
                float rU1 = (sU1 + sV2) * pB2, rV1 = fmaf(af1, sV2, sV1 + sU1) * pA21;
                // step 4 (row t+3): pair j
                float qU = (rU0 + rV1) * pB3, qV = fmaf(af0, rV1, rV0 + rU0) * pA30;
                aU = (hasU && qU > 0.f) ? m + lg2f(qU) : NEG2;
                aV = (hasV && qV > 0.f) ? m + lg2f(qV) : NEG2;
                ab[rb ^ 1][4 + j] = make_float2(aU, aV);
            }
            rb ^= 1;
        }
        if (w == 4) { asm volatile("cp.async.wait_group 0;" ::: "memory"); }
        for (; t <= Tm; t++) {           // tail single steps (log domain)
            __syncthreads();
            if (cw) {
                float2 n1 = ab[rb][3 + j];
                const float* R = &ring[t & 15][0];
                float eB = R[0], eV = R[c0];
                acc += ex2f(eV * LOG2E);
                float nU = lse2p(aU, n1.y, eB);
                float nV = lse3p(aV, aU, (af0 > 0.5f) ? n1.y : NEG2, eV);
                aU = hasU ? nU : NEG2;
                aV = hasV ? nV : NEG2;
                ab[rb ^ 1][4 + j] = make_float2(aU, aV);
            }
            rb ^= 1;
        }
    } else {
        // ======================= BACKWARD =======================
        int c0 = 0, c1 = 0, c2 = 0, c3 = 0, c4 = 0;
        float aN0 = 0.f, aN1 = 0.f, aN2 = 0.f, aN3 = 0.f;
        if (cw) {
            if (j     < L) c0 = targets[bL + j];
            if (j + 1 < L) c1 = targets[bL + j + 1];
            if (j + 2 < L) c2 = targets[bL + j + 2];
            if (j + 3 < L) c3 = targets[bL + j + 3];
            if (j + 4 < L) c4 = targets[bL + j + 4];
            aN0 = (j + 1 < L && c1 != c0) ? 1.f : 0.f;
            aN1 = (j + 2 < L && c2 != c1) ? 1.f : 0.f;
            aN2 = (j + 3 < L && c3 != c2) ? 1.f : 0.f;
            aN3 = (j + 4 < L && c4 != c3) ? 1.f : 0.f;
        }
        if (w == 4) {
            #pragma unroll
            for (int i = 0; i < 13; i++) {
                if (i < nB) ISSUE(i & 15, len - 1 - i)
                asm volatile("cp.async.commit_group;" ::: "memory");
            }
            asm volatile("cp.async.wait_group 8;" ::: "memory");
        }
        __syncthreads();
        if (cw) {
            aU = (j == tl)     ? 0.f : NEG2;
            aV = (j == tl - 1) ? 0.f : NEG2;
            ab[0][j] = make_float2(aU, aV);
        }
        int rb = 0, k = 0;
        for (; k + 3 <= nB - 1; k += 4) {
            __syncthreads();
            if (w == 4) {
                #pragma unroll
                for (int q = 0; q < 4; q++) {
                    int i = k + 12 + q;
                    if (i < nB) ISSUE(i & 15, len - 1 - i)
                    asm volatile("cp.async.commit_group;" ::: "memory");
                }
                asm volatile("cp.async.wait_group 8;" ::: "memory");
            } else if (cw) {
                float2 n1 = ab[rb][j + 1], n2 = ab[rb][j + 2];
                float2 n3 = ab[rb][j + 3], n4 = ab[rb][j + 4];
                float m = fmaxf(fmaxf(fmaxf(aU, aV), fmaxf(n1.x, n1.y)),
                                fmaxf(fmaxf(n2.x, n2.y),
                                      fmaxf(fmaxf(n3.x, n3.y), fmaxf(n4.x, n4.y))));
                float U0 = ex2f(aU - m),   V0 = ex2f(aV - m);
                float U1 = ex2f(n1.x - m), V1 = ex2f(n1.y - m);
                float U2 = ex2f(n2.x - m), V2 = ex2f(n2.y - m);
                float U3 = ex2f(n3.x - m), V3 = ex2f(n3.y - m);
                float U4 = ex2f(n4.x - m), V4 = ex2f(n4.y - m);
                const float* R0 = &ring[(k    ) & 15][0];
                const float* R1 = &ring[(k + 1) & 15][0];
                const float* R2 = &ring[(k + 2) & 15][0];
                const float* R3 = &ring[(k + 3) & 15][0];
                float pB0 = ex2f(R0[0] * LOG2E), pB1 = ex2f(R1[0] * LOG2E);
                float pB2 = ex2f(R2[0] * LOG2E), pB3 = ex2f(R3[0] * LOG2E);
                float pA00 = ex2f(R0[c0] * LOG2E), pA01 = ex2f(R0[c1] * LOG2E);
                float pA02 = ex2f(R0[c2] * LOG2E), pA03 = ex2f(R0[c3] * LOG2E);
                float pA04 = ex2f(R0[c4] * LOG2E);
                float pA10 = ex2f(R1[c0] * LOG2E), pA11 = ex2f(R1[c1] * LOG2E);
                float pA12 = ex2f(R1[c2] * LOG2E), pA13 = ex2f(R1[c3] * LOG2E);
                float pA20 = ex2f(R2[c0] * LOG2E), pA21 = ex2f(R2[c1] * LOG2E);
                float pA22 = ex2f(R2[c2] * LOG2E);
                float pA30 = ex2f(R3[c0] * LOG2E), pA31 = ex2f(R3[c1] * LOG2E);
                acc += pA00 + pA10 + pA20 + pA30;
                // step 1 (row len-1-k): pairs j..j+3
                float w0 = V0 * pA00, w1 = V1 * pA01, w2 = V2 * pA02,
                      w3 = V3 * pA03, w4 = V4 * pA04;
                float tU0 = fmaf(U0, pB0, w0), tV0 = fmaf(aN0, w1, fmaf(U1, pB0, w0));
                float tU1 = fmaf(U1, pB0, w1), tV1 = fmaf(aN1, w2, fmaf(U2, pB0, w1));
                float tU2 = fmaf(U2, pB0, w2), tV2 = fmaf(aN2, w3, fmaf(U3, pB0, w2));
                float tU3 = fmaf(U3, pB0, w3), tV3 = fmaf(aN3, w4, fmaf(U4, pB0, w3));
                // step 2: pairs j..j+2
                float x0 = tV0 * pA10, x1 = tV1 * pA11, x2 = tV2 * pA12, x3 = tV3 * pA13;
                float sU0 = fmaf(tU0, pB1, x0), sV0 = fmaf(aN0, x1, fmaf(tU1, pB1, x0));
                float sU1 = fmaf(tU1, pB1, x1), sV1 = fmaf(aN1, x2, fmaf(tU2, pB1, x1));
                float sU2 = fmaf(tU2, pB1, x2), sV2 = fmaf(aN2, x3, fmaf(tU3, pB1, x2));
                // step 3: pairs j..j+1
                float y0 = sV0 * pA20, y1 = sV1 * pA21, y2 = sV2 * pA22;
                float rU0 = fmaf(sU0, pB2, y0), rV0 = fmaf(aN0, y1, fmaf(sU1, pB2, y0));
                float rU1 = fmaf(sU1, pB2, y1), rV1 = fmaf(aN1, y2, fmaf(sU2, pB2, y1));
                // step 4: pair j
                float z0 = rV0 * pA30, z1 = rV1 * pA31;
                float qU = fmaf(rU0, pB3, z0), qV = fmaf(aN0, z1, fmaf(rU1, pB3, z0));
                aU = (hasU && qU > 0.f) ? m + lg2f(qU) : NEG2;
                aV = (hasV && qV > 0.f) ? m + lg2f(qV) : NEG2;
                ab[rb ^ 1][j] = make_float2(aU, aV);
            }
            rb ^= 1;
        }
        if (w == 4) { asm volatile("cp.async.wait_group 0;" ::: "memory"); }
        for (; k <= nB - 1; k++) {       // tail single steps (log domain)
            __syncthreads();
            if (cw) {
                float2 n1 = ab[rb][j + 1];
                const float* R = &ring[k & 15][0];
                float eB = R[0] * LOG2E, eA = R[c0] * LOG2E, eC = R[c1] * LOG2E;
                acc += ex2f(eA);
                float nU = lse2(aU + eB, aV + eA);
                float nV = lse3(aV + eA, n1.x + eB, (aN0 > 0.5f) ? (n1.y + eC) : NEG2);
                aU = hasU ? nU : NEG2;
                aV = hasV ? nV : NEG2;
                ab[rb ^ 1][j] = make_float2(aU, aV);
            }
            rb ^= 1;
        }
    }

    // ---- publish mid-state + tps partials ----
    if (cw) {
        g_mid[b][dir][j][0] = aU;
        g_mid[b][dir][j][1] = aV;
        g_tps[b][dir][j]    = acc;
    }
    __threadfence();
    __syncthreads();
    if (tid == 0) sflag = atomicAdd(&g_done[b], 1u);
    __syncthreads();

    if (sflag == 1) {                    // second finisher: combine this sample
        float cU = NEG2, cV = NEG2, mj = NEG2;
        if (cw) {
            float a0 = __ldcg(&g_mid[b][0][j][0]), a1 = __ldcg(&g_mid[b][0][j][1]);
            float b0 = __ldcg(&g_mid[b][1][j][0]), b1 = __ldcg(&g_mid[b][1][j][1]);
            cU = a0 + b0;  cV = a1 + b1;
            mj = fmaxf(cU, cV);
            #pragma unroll
            for (int o = 16; o; o >>= 1) mj = fmaxf(mj, __shfl_xor_sync(0xFFFFFFFFu, mj, o));
            if (lane == 0) redm[w] = mj;
        }
        __syncthreads();
        float M = fmaxf(fmaxf(redm[0], redm[1]), fmaxf(redm[2], redm[3]));
        float sj = 0.0f, wgt = 0.0f;
        if (cw) {
            sj = ex2f(cU - M) + ex2f(cV - M);
            if (j < L) {
                float tps = __ldcg(&g_tps[b][0][j]) + __ldcg(&g_tps[b][1][j]);
                float om  = 1.0f - tps * (1.0f / (float)T);
                wgt = om * om;                       // GAMMA = 2
            }
            #pragma unroll
            for (int o = 16; o; o >>= 1) {
                sj  += __shfl_xor_sync(0xFFFFFFFFu, sj, o);
                wgt += __shfl_xor_sync(0xFFFFFFFFu, wgt, o);
            }
            if (lane == 0) { reds[w] = sj; redww[w] = wgt; }
        }
        __syncthreads();
        if (tid == 0) {
            float ss = reds[0] + reds[1] + reds[2] + reds[3];
            float ll = (M + lg2f(ss)) * LN2;
            g_loss[b] = (ll > -5e29f) ? -ll : 0.0f;   // zero_infinity
            g_wsum[b] = redww[0] + redww[1] + redww[2] + redww[3];
            g_done[b] = 0;                            // reset for graph replay
            finalize(out, B, L);
        }
    }
    #undef ISSUE
}

extern "C" void kernel_launch(void* const* d_in, const int* in_sizes, int n_in,
                              void* d_out, int out_size)
{
    const float* lp      = (const float*)d_in[0];
    const int*   targets = (const int*)d_in[1];
    const int*   in_len  = (const int*)d_in[2];
    const int*   tg_len  = (const int*)d_in[3];

    int B = in_sizes[2];                 // 64
    int L = in_sizes[1] / B;             // 100
    int T = in_sizes[0] / (B * CFIX);    // 1000

    focal_ctc_kernel<<<2 * B, 160>>>(lp, targets, in_len, tg_len, (float*)d_out, T, B, L);
}